// round 14
// baseline (speedup 1.0000x reference)
#include <cuda_runtime.h>
#include <math.h>

#define H 128
#define B 512
#define RANKS 3
#define POOL_BLOCKS_X 512
#define POOL_THREADS 256
#define POOL_WARPS_PER_RANK (POOL_BLOCKS_X * POOL_THREADS / 32)

// ---------------- scratch (no allocations allowed) ----------------
__device__ float g_sum [RANKS][B * H];
__device__ float g_gsum[RANKS][B * H];
__device__ float g_max [RANKS][B * H];
__device__ float g_cnt [RANKS][B];
__device__ float g_state[B][3 * H];

__device__ __forceinline__ void atomicMaxF(float* addr, float v) {
    if (v >= 0.f) atomicMax((int*)addr, __float_as_int(v));
    else          atomicMin((unsigned int*)addr, __float_as_uint(v));
}

// ---------------- init: reset accumulators every replay ----------------
__global__ void init_kernel() {
    int i = blockIdx.x * blockDim.x + threadIdx.x;
    int stride = gridDim.x * blockDim.x;
    int tot = RANKS * B * H;
    for (int idx = i; idx < tot; idx += stride) {
        int r = idx / (B * H);
        int o = idx - r * (B * H);
        g_sum[r][o]  = 0.f;
        g_gsum[r][o] = 0.f;
        g_max[r][o]  = -INFINITY;
    }
    if (i < RANKS * B) g_cnt[i / B][i % B] = 0.f;
}

// ---------------- stage 1: fused gated multi-agg pooling (all 3 ranks) ----
__global__ void __launch_bounds__(POOL_THREADS)
pool_kernel(const float* __restrict__ h0, const float* __restrict__ h1,
            const float* __restrict__ h2,
            const int* __restrict__ bb0, const int* __restrict__ bb1,
            const int* __restrict__ bb2,
            const float* __restrict__ Wg0, const float* __restrict__ Wg1,
            const float* __restrict__ Wg2,
            const float* __restrict__ bgp0, const float* __restrict__ bgp1,
            const float* __restrict__ bgp2,
            int N0, int N1, int N2) {
    int rank = blockIdx.y;
    const float* __restrict__ h  = (rank == 0) ? h0  : (rank == 1) ? h1  : h2;
    const int*   __restrict__ b  = (rank == 0) ? bb0 : (rank == 1) ? bb1 : bb2;
    const float* __restrict__ Wg = (rank == 0) ? Wg0 : (rank == 1) ? Wg1 : Wg2;
    const float* __restrict__ bg = (rank == 0) ? bgp0 : (rank == 1) ? bgp1 : bgp2;
    int N = (rank == 0) ? N0 : (rank == 1) ? N1 : N2;

    int npw = (N + POOL_WARPS_PER_RANK - 1) / POOL_WARPS_PER_RANK;
    int gwid = (blockIdx.x * blockDim.x + threadIdx.x) >> 5;
    int lane = threadIdx.x & 31;
    int start = gwid * npw;
    if (start >= N) return;
    int end = min(N, start + npw);

    float4 wg = reinterpret_cast<const float4*>(Wg)[lane];
    float bgv = bg[0];

    float* __restrict__ sums  = g_sum[rank];
    float* __restrict__ gsums = g_gsum[rank];
    float* __restrict__ maxs  = g_max[rank];
    float* __restrict__ cnts  = g_cnt[rank];

    const float4* __restrict__ h4 = reinterpret_cast<const float4*>(h);

    int cur = b[start];
    float4 s4  = make_float4(0.f, 0.f, 0.f, 0.f);
    float4 gs4 = make_float4(0.f, 0.f, 0.f, 0.f);
    float4 m4  = make_float4(-INFINITY, -INFINITY, -INFINITY, -INFINITY);
    float  c   = 0.f;

    auto flush = [&]() {
        int base = cur * H + (lane << 2);
        atomicAdd(&sums[base + 0], s4.x);
        atomicAdd(&sums[base + 1], s4.y);
        atomicAdd(&sums[base + 2], s4.z);
        atomicAdd(&sums[base + 3], s4.w);
        atomicAdd(&gsums[base + 0], gs4.x);
        atomicAdd(&gsums[base + 1], gs4.y);
        atomicAdd(&gsums[base + 2], gs4.z);
        atomicAdd(&gsums[base + 3], gs4.w);
        atomicMaxF(&maxs[base + 0], m4.x);
        atomicMaxF(&maxs[base + 1], m4.y);
        atomicMaxF(&maxs[base + 2], m4.z);
        atomicMaxF(&maxs[base + 3], m4.w);
        if (lane == 0) atomicAdd(&cnts[cur], c);
    };

    auto acc1 = [&](const float4& v, float g) {
        s4.x += v.x;  s4.y += v.y;  s4.z += v.z;  s4.w += v.w;
        m4.x = fmaxf(m4.x, v.x);  m4.y = fmaxf(m4.y, v.y);
        m4.z = fmaxf(m4.z, v.z);  m4.w = fmaxf(m4.w, v.w);
        gs4.x += g * v.x;  gs4.y += g * v.y;
        gs4.z += g * v.z;  gs4.w += g * v.w;
        c += 1.f;
    };

    int n = start;
    while (n < end) {
        if (n + 8 <= end) {
            int same = 1;
            #pragma unroll
            for (int u = 0; u < 8; ++u) same &= (b[n + u] == cur);
            if (same) {
                float4 v[8];
                #pragma unroll
                for (int u = 0; u < 8; ++u)
                    v[u] = __ldcs(&h4[(n + u) * 32 + lane]);
                float p[8];
                #pragma unroll
                for (int u = 0; u < 8; ++u)
                    p[u] = v[u].x * wg.x + v[u].y * wg.y + v[u].z * wg.z + v[u].w * wg.w;
                #pragma unroll
                for (int o = 16; o; o >>= 1) {
                    #pragma unroll
                    for (int u = 0; u < 8; ++u)
                        p[u] += __shfl_xor_sync(0xffffffffu, p[u], o);
                }
                #pragma unroll
                for (int u = 0; u < 8; ++u) {
                    float g = 1.f / (1.f + __expf(-(p[u] + bgv)));
                    acc1(v[u], g);
                }
                n += 8;
                continue;
            }
        }
        int seg = b[n];
        float4 v = __ldcs(&h4[n * 32 + lane]);
        if (seg != cur) {
            flush();
            s4  = make_float4(0.f, 0.f, 0.f, 0.f);
            gs4 = make_float4(0.f, 0.f, 0.f, 0.f);
            m4  = make_float4(-INFINITY, -INFINITY, -INFINITY, -INFINITY);
            c   = 0.f;
            cur = seg;
        }
        float p = v.x * wg.x + v.y * wg.y + v.z * wg.z + v.w * wg.w;
        #pragma unroll
        for (int o = 16; o; o >>= 1) p += __shfl_xor_sync(0xffffffffu, p, o);
        float g = 1.f / (1.f + __expf(-(p + bgv)));
        acc1(v, g);
        ++n;
    }
    flush();
}

// ---------------- stage 2: fully fused epilogue ---------------------------
// 64 blocks x 512 threads, 8 segments per block. Per block:
//   for rank 0..2: stage agg[8][512] -> 8-way split-K GEMM -> g_state slice
//   LayerNorm + SiLU (warps 0-7, one row each)
//   MLP 384->128 (8-way split-K) + SiLU + *W2 -> per-row dot -> out
// Thread map for GEMMs: cg = tid&31 (4 output cols, coalesced LDG.128
// weights), kc = (tid>>5)&7 (K chunk), sg = tid>>8 (4-segment group).
// A-tile reads are warp-uniform -> broadcast LDS (no conflict penalty).
__global__ void __launch_bounds__(512)
epilogue_kernel(const float* __restrict__ Wp0, const float* __restrict__ bp0,
                const float* __restrict__ Wp1, const float* __restrict__ bp1,
                const float* __restrict__ Wp2, const float* __restrict__ bp2,
                const float* __restrict__ gamma, const float* __restrict__ beta,
                const float* __restrict__ W1,  const float* __restrict__ b1f,
                const float* __restrict__ W2,  const float* __restrict__ b2f,
                float* __restrict__ out) {
    int seg0 = blockIdx.x * 8;
    int tid  = threadIdx.x;
    int wid  = tid >> 5;
    int lane = tid & 31;

    __shared__ float sa[8][512];      // 16 KB: agg tile, later LN rows (384)
    __shared__ float rp[7][8][128];   // 28 KB: split-K partials (kc 1..7)
    __shared__ float csh[8];

    int cg = tid & 31;
    int kc = (tid >> 5) & 7;
    int sg = tid >> 8;                // 0 or 1 -> segments sg*4 .. sg*4+3
    int j  = cg * 4;

    // ---------- per-rank projection ----------
    for (int rank = 0; rank < RANKS; ++rank) {
        const float* Wp = (rank == 0) ? Wp0 : (rank == 1) ? Wp1 : Wp2;
        const float* bp = (rank == 0) ? bp0 : (rank == 1) ? bp1 : bp2;
        const float* __restrict__ sums  = g_sum[rank];
        const float* __restrict__ gsums = g_gsum[rank];
        const float* __restrict__ maxs  = g_max[rank];

        if (tid < 8) csh[tid] = g_cnt[rank][seg0 + tid];
        __syncthreads();

        for (int idx = tid; idx < 8 * 512; idx += 512) {
            int s = idx >> 9;
            int k = idx & 511;
            int seg = seg0 + s;
            float v;
            if (k < 128)      v = sums[seg * H + k];
            else if (k < 256) v = sums[seg * H + (k - 128)] / fmaxf(csh[s], 1.f);
            else if (k < 384) v = (csh[s] > 0.f) ? maxs[seg * H + (k - 256)] : 0.f;
            else              v = gsums[seg * H + (k - 384)];
            sa[s][k] = v;
        }
        __syncthreads();

        float4 r[4];
        #pragma unroll
        for (int s4 = 0; s4 < 4; ++s4) r[s4] = make_float4(0.f, 0.f, 0.f, 0.f);

        const float4* W4 = reinterpret_cast<const float4*>(Wp) + cg;
        int k0 = kc * 64;
        #pragma unroll 4
        for (int kk = 0; kk < 16; ++kk) {
            int kb = k0 + kk * 4;
            float4 w0 = W4[(kb + 0) * 32];
            float4 w1 = W4[(kb + 1) * 32];
            float4 w2 = W4[(kb + 2) * 32];
            float4 w3 = W4[(kb + 3) * 32];
            #pragma unroll
            for (int s4 = 0; s4 < 4; ++s4) {
                float4 av = *reinterpret_cast<const float4*>(&sa[sg * 4 + s4][kb]);
                r[s4].x += av.x * w0.x + av.y * w1.x + av.z * w2.x + av.w * w3.x;
                r[s4].y += av.x * w0.y + av.y * w1.y + av.z * w2.y + av.w * w3.y;
                r[s4].z += av.x * w0.z + av.y * w1.z + av.z * w2.z + av.w * w3.z;
                r[s4].w += av.x * w0.w + av.y * w1.w + av.z * w2.w + av.w * w3.w;
            }
        }

        if (kc > 0) {
            #pragma unroll
            for (int s4 = 0; s4 < 4; ++s4)
                *reinterpret_cast<float4*>(&rp[kc - 1][sg * 4 + s4][j]) = r[s4];
        }
        __syncthreads();
        if (kc == 0) {
            float4 bpj = *(reinterpret_cast<const float4*>(bp) + cg);
            #pragma unroll
            for (int s4 = 0; s4 < 4; ++s4) {
                int s = sg * 4 + s4;
                float4 acc = r[s4];
                #pragma unroll
                for (int c = 0; c < 7; ++c) {
                    float4 p = *reinterpret_cast<const float4*>(&rp[c][s][j]);
                    acc.x += p.x; acc.y += p.y; acc.z += p.z; acc.w += p.w;
                }
                acc.x += bpj.x; acc.y += bpj.y; acc.z += bpj.z; acc.w += bpj.w;
                *reinterpret_cast<float4*>(&g_state[seg0 + s][rank * H + j]) = acc;
            }
        }
        __syncthreads();
    }

    // ---------- LayerNorm + SiLU (warps 0..7, row = wid) ----------
    if (wid < 8) {
        int s = wid;
        const float* row = g_state[seg0 + s];
        float vals[12];
        float ps = 0.f;
        #pragma unroll
        for (int kk = 0; kk < 12; ++kk) {
            vals[kk] = row[lane + kk * 32];
            ps += vals[kk];
        }
        #pragma unroll
        for (int o = 16; o; o >>= 1) ps += __shfl_xor_sync(0xffffffffu, ps, o);
        float mu = ps * (1.f / 384.f);
        float pv = 0.f;
        #pragma unroll
        for (int kk = 0; kk < 12; ++kk) {
            float d = vals[kk] - mu;
            pv += d * d;
        }
        #pragma unroll
        for (int o = 16; o; o >>= 1) pv += __shfl_xor_sync(0xffffffffu, pv, o);
        float rstd = rsqrtf(pv * (1.f / 384.f) + 1e-5f);
        #pragma unroll
        for (int kk = 0; kk < 12; ++kk) {
            int k = lane + kk * 32;
            float xn = (vals[kk] - mu) * rstd * gamma[k] + beta[k];
            sa[s][k] = xn / (1.f + __expf(-xn));   // silu
        }
    }
    __syncthreads();

    // ---------- MLP 384->128 (8-way split-K over 48-wide chunks) ----------
    float4 r[4];
    #pragma unroll
    for (int s4 = 0; s4 < 4; ++s4) r[s4] = make_float4(0.f, 0.f, 0.f, 0.f);

    const float4* W14 = reinterpret_cast<const float4*>(W1) + cg;
    int k0c = kc * 48;
    #pragma unroll 4
    for (int kk = 0; kk < 12; ++kk) {
        int kb = k0c + kk * 4;
        float4 w0 = W14[(kb + 0) * 32];
        float4 w1 = W14[(kb + 1) * 32];
        float4 w2 = W14[(kb + 2) * 32];
        float4 w3 = W14[(kb + 3) * 32];
        #pragma unroll
        for (int s4 = 0; s4 < 4; ++s4) {
            float4 av = *reinterpret_cast<const float4*>(&sa[sg * 4 + s4][kb]);
            r[s4].x += av.x * w0.x + av.y * w1.x + av.z * w2.x + av.w * w3.x;
            r[s4].y += av.x * w0.y + av.y * w1.y + av.z * w2.y + av.w * w3.y;
            r[s4].z += av.x * w0.z + av.y * w1.z + av.z * w2.z + av.w * w3.z;
            r[s4].w += av.x * w0.w + av.y * w1.w + av.z * w2.w + av.w * w3.w;
        }
    }

    if (kc > 0) {
        #pragma unroll
        for (int s4 = 0; s4 < 4; ++s4)
            *reinterpret_cast<float4*>(&rp[kc - 1][sg * 4 + s4][j]) = r[s4];
    }
    __syncthreads();

    // fo aliases rp[0]: each (s,j) read before overwrite by the same thread
    float* fo = &rp[0][0][0];   // [8][128]
    if (kc == 0) {
        float4 b1j = *(reinterpret_cast<const float4*>(b1f) + cg);
        float4 w2j = *(reinterpret_cast<const float4*>(W2) + cg);
        #pragma unroll
        for (int s4 = 0; s4 < 4; ++s4) {
            int s = sg * 4 + s4;
            float4 acc = r[s4];
            #pragma unroll
            for (int c = 0; c < 7; ++c) {
                float4 p = *reinterpret_cast<const float4*>(&rp[c][s][j]);
                acc.x += p.x; acc.y += p.y; acc.z += p.z; acc.w += p.w;
            }
            acc.x += b1j.x; acc.y += b1j.y; acc.z += b1j.z; acc.w += b1j.w;
            acc.x = acc.x / (1.f + __expf(-acc.x));
            acc.y = acc.y / (1.f + __expf(-acc.y));
            acc.z = acc.z / (1.f + __expf(-acc.z));
            acc.w = acc.w / (1.f + __expf(-acc.w));
            fo[s * 128 + j + 0] = acc.x * w2j.x;
            fo[s * 128 + j + 1] = acc.y * w2j.y;
            fo[s * 128 + j + 2] = acc.z * w2j.z;
            fo[s * 128 + j + 3] = acc.w * w2j.w;
        }
    }
    __syncthreads();

    if (wid < 8) {
        int s = wid;
        float p = fo[s * 128 + lane] + fo[s * 128 + lane + 32]
                + fo[s * 128 + lane + 64] + fo[s * 128 + lane + 96];
        #pragma unroll
        for (int o = 16; o; o >>= 1) p += __shfl_xor_sync(0xffffffffu, p, o);
        if (lane == 0) out[seg0 + s] = p + b2f[0];
    }
}

// ---------------- launch ----------------
extern "C" void kernel_launch(void* const* d_in, const int* in_sizes, int n_in,
                              void* d_out, int out_size) {
    const float* h0  = (const float*)d_in[0];
    const float* h1  = (const float*)d_in[1];
    const float* h2  = (const float*)d_in[2];
    const int*   b0  = (const int*)d_in[3];
    const int*   b1  = (const int*)d_in[4];
    const int*   b2  = (const int*)d_in[5];
    const float* Wg0 = (const float*)d_in[6];
    const float* bg0 = (const float*)d_in[7];
    const float* Wg1 = (const float*)d_in[8];
    const float* bg1 = (const float*)d_in[9];
    const float* Wg2 = (const float*)d_in[10];
    const float* bg2 = (const float*)d_in[11];
    const float* Wp0 = (const float*)d_in[12];
    const float* bp0 = (const float*)d_in[13];
    const float* Wp1 = (const float*)d_in[14];
    const float* bp1 = (const float*)d_in[15];
    const float* Wp2 = (const float*)d_in[16];
    const float* bp2 = (const float*)d_in[17];
    const float* gamma = (const float*)d_in[18];
    const float* beta  = (const float*)d_in[19];
    const float* W1  = (const float*)d_in[20];
    const float* b1f = (const float*)d_in[21];
    const float* W2  = (const float*)d_in[22];
    const float* b2f = (const float*)d_in[23];

    int N0 = in_sizes[3];
    int N1 = in_sizes[4];
    int N2 = in_sizes[5];

    init_kernel<<<384, 256>>>();

    dim3 gpool(POOL_BLOCKS_X, RANKS);
    pool_kernel<<<gpool, POOL_THREADS>>>(h0, h1, h2, b0, b1, b2,
                                         Wg0, Wg1, Wg2, bg0, bg1, bg2,
                                         N0, N1, N2);

    epilogue_kernel<<<B / 8, 512>>>(Wp0, bp0, Wp1, bp1, Wp2, bp2,
                                    gamma, beta, W1, b1f, W2, b2f,
                                    (float*)d_out);
}